// round 16
// baseline (speedup 1.0000x reference)
#include <cuda_runtime.h>
#include <math.h>

#define Bn 12
#define HW1 45056           // 128*352
#define N5 11264            // 64*176
#define W5i 176
#define BEVC 64
#define OUT_MAIN (12*128*128*128)   // 25165824

typedef unsigned long long u64;

// packed f32x2 helpers (sm_103a)
__device__ __forceinline__ u64 pack2(float lo, float hi) {
    u64 r; asm("mov.b64 %0, {%1, %2};" : "=l"(r) : "f"(lo), "f"(hi)); return r;
}
__device__ __forceinline__ void fma2(u64 &d, u64 a, u64 b) {
    asm("fma.rn.f32x2 %0, %1, %2, %0;" : "+l"(d) : "l"(a), "l"(b));
}
__device__ __forceinline__ float2 unpack2(u64 v) {
    float2 r; asm("mov.b64 {%0, %1}, %2;" : "=f"(r.x), "=f"(r.y) : "l"(v)); return r;
}

// BEV scratch, channels-last: [B][128][128][64]
__device__ float g_bev[Bn * 128 * 128 * BEVC];
// transposed weights
__device__ __align__(16) float g_wt [9 * 64 * 128];   // conv: [kk][ic][oc]
__device__ __align__(16) float g_wct[512 * 112];      // lift: [c][o] (64 red + 48 dep)

// ---------------------------------------------------------------------------
// kWt: transpose conv weights + build combined lift weight matrix.
// 73728 + 57344 = 131072 elements = 512 blocks x 256.
// ---------------------------------------------------------------------------
__global__ void kWt(const float* __restrict__ w,
                    const float* __restrict__ w5, const float* __restrict__ wd)
{
    int i = blockIdx.x * 256 + threadIdx.x;
    if (i < 73728) {
        int oc = i & 127;
        int t  = i >> 7;
        int ic = t & 63;
        int kk = t >> 6;
        g_wt[i] = w[(oc*64 + ic)*9 + kk];
    } else {
        int j = i - 73728;          // < 57344
        int o = j % 112, c = j / 112;
        g_wct[j] = (o < 64) ? w5[o*512 + c] : wd[(o-64)*512 + c];
    }
}

// ---------------------------------------------------------------------------
// Kernel A: fused skip path, 2 px/thread, circular prefetch depth 4.
// ---------------------------------------------------------------------------
__global__ __launch_bounds__(128, 2)
void kA(const float* __restrict__ stage1,
        const float* __restrict__ w1, const float* __restrict__ g1, const float* __restrict__ b1,
        const float* __restrict__ w2, const float* __restrict__ g2, const float* __restrict__ b2,
        float* __restrict__ skip_out)
{
    __shared__ __align__(16) float w1T[64*64];   // [c][o]
    __shared__ __align__(16) float w2T[64*32];   // [o][s]
    __shared__ float sg1[64], sb1[64], sg2[32], sb2[32];
    int tid = threadIdx.x;
    for (int i = tid; i < 64*64; i += 128) { int o = i & 63, c = i >> 6; w1T[c*64+o] = w1[o*64+c]; }
    for (int i = tid; i < 64*32; i += 128) { int s = i & 31, o = i >> 5; w2T[o*32+s] = w2[s*64+o]; }
    if (tid < 64) { sg1[tid] = g1[tid]; sb1[tid] = b1[tid]; }
    if (tid < 32) { sg2[tid] = g2[tid]; sb2[tid] = b2[tid]; }
    __syncthreads();

    int gid = blockIdx.x * 256 + tid;
    int b = gid / HW1;
    int p = gid - b * HW1;
    const float* xin = stage1 + (size_t)b * 64 * HW1 + p;

    u64 acc[2][32];
    #pragma unroll
    for (int q = 0; q < 32; q++) { acc[0][q] = 0ull; acc[1][q] = 0ull; }

    const ulonglong2* w1T2 = (const ulonglong2*)w1T;
    float pa[4], pb[4];
    {
        const float* xp0 = xin;
        #pragma unroll
        for (int d = 0; d < 4; d++) { pa[d] = xp0[0]; pb[d] = xp0[128]; xp0 += HW1; }
    }
    const float* xp = xin + (size_t)4 * HW1;
    int ch = 4;
    for (int c = 0; c < 64; c += 4) {
        #pragma unroll
        for (int u = 0; u < 4; u++) {
            const float* xq = (ch < 64) ? xp : (xin + (size_t)63 * HW1);
            float na = xq[0], nb = xq[128];
            u64 x0 = pack2(pa[u], pa[u]);
            u64 x1 = pack2(pb[u], pb[u]);
            const ulonglong2* wrow = w1T2 + (c + u) * 16;
            #pragma unroll
            for (int q = 0; q < 16; q++) {
                ulonglong2 wp = wrow[q];
                fma2(acc[0][q*2+0], x0, wp.x);
                fma2(acc[0][q*2+1], x0, wp.y);
                fma2(acc[1][q*2+0], x1, wp.x);
                fma2(acc[1][q*2+1], x1, wp.y);
            }
            pa[u] = na; pb[u] = nb;
            xp += HW1; ch++;
        }
    }

    const ulonglong2* w2T2 = (const ulonglong2*)w2T;
    #pragma unroll
    for (int px = 0; px < 2; px++) {
        u64 sacc2[16];
        #pragma unroll
        for (int s = 0; s < 16; s++) sacc2[s] = 0ull;
        #pragma unroll
        for (int q = 0; q < 32; q++) {
            float2 a = unpack2(acc[px][q]);
            int o = 2*q;
            float v0 = fmaxf(a.x * sg1[o]   + sb1[o],   0.f);
            float v1 = fmaxf(a.y * sg1[o+1] + sb1[o+1], 0.f);
            u64 v0p = pack2(v0, v0);
            u64 v1p = pack2(v1, v1);
            #pragma unroll
            for (int s4 = 0; s4 < 8; s4++) {
                ulonglong2 wp0 = w2T2[o*8 + s4];
                fma2(sacc2[s4*2+0], v0p, wp0.x);
                fma2(sacc2[s4*2+1], v0p, wp0.y);
            }
            #pragma unroll
            for (int s4 = 0; s4 < 8; s4++) {
                ulonglong2 wp1 = w2T2[(o+1)*8 + s4];
                fma2(sacc2[s4*2+0], v1p, wp1.x);
                fma2(sacc2[s4*2+1], v1p, wp1.y);
            }
        }
        float* op = skip_out + (size_t)b * 32 * HW1 + p + px * 128;
        #pragma unroll
        for (int s = 0; s < 16; s++) {
            float2 a = unpack2(sacc2[s]);
            op[(size_t)(2*s+0) * HW1] = fmaxf(a.x * sg2[2*s+0] + sb2[2*s+0], 0.f);
            op[(size_t)(2*s+1) * HW1] = fmaxf(a.y * sg2[2*s+1] + sb2[2*s+1], 0.f);
        }
    }
}

// ---------------------------------------------------------------------------
// Kernel B (fused lift): 112-output GEMM (1 px/thread) + softmax depth +
// geometry + direct scatter.  Single pass over stage5.
// ---------------------------------------------------------------------------
__global__ __launch_bounds__(128, 2)
void kB(const float* __restrict__ stage5,
        const float* __restrict__ g5, const float* __restrict__ b5,
        const float* __restrict__ gd, const float* __restrict__ bd,
        const float* __restrict__ intr, const float* __restrict__ extr)
{
    __shared__ __align__(16) float ws[64*112];   // [c][o]
    __shared__ float sg5[64], sb5[64], sgd[48], sbd[48];
    int tid = threadIdx.x;
    if (tid < 64) { sg5[tid] = g5[tid]; sb5[tid] = b5[tid]; }
    if (tid < 48) { sgd[tid] = gd[tid]; sbd[tid] = bd[tid]; }
    int b = blockIdx.x / 88;
    int p = (blockIdx.x - b * 88) * 128 + tid;
    const float* xin = stage5 + (size_t)b * 512 * N5 + p;

    u64 acc2[56];
    #pragma unroll
    for (int i = 0; i < 56; i++) acc2[i] = 0ull;

    for (int c0 = 0; c0 < 512; c0 += 64) {
        __syncthreads();
        {
            const float4* src = (const float4*)(g_wct + c0*112);
            float4* dst = (float4*)ws;
            for (int i = tid; i < 1792; i += 128) dst[i] = src[i];
        }
        __syncthreads();
        const ulonglong2* ws2 = (const ulonglong2*)ws;
        float pf[4];
        {
            const float* xp0 = xin + (size_t)c0 * N5;
            #pragma unroll
            for (int d = 0; d < 4; d++) { pf[d] = xp0[0]; xp0 += N5; }
        }
        const float* xp = xin + (size_t)(c0 + 4) * N5;
        int ch = c0 + 4;
        for (int c = 0; c < 64; c += 4) {
            #pragma unroll
            for (int u = 0; u < 4; u++) {
                const float* xq = (ch < 512) ? xp : (xin + (size_t)511 * N5);
                float nx = xq[0];
                u64 xv2 = pack2(pf[u], pf[u]);
                const ulonglong2* wrow = ws2 + (c + u) * 28;
                #pragma unroll
                for (int q = 0; q < 28; q++) {
                    ulonglong2 wp = wrow[q];
                    fma2(acc2[q*2+0], xv2, wp.x);
                    fma2(acc2[q*2+1], xv2, wp.y);
                }
                pf[u] = nx;
                xp += N5; ch++;
            }
        }
    }

    // depth logits (outputs 64..111 = acc2[32..55]) -> softmax -> depth
    float m = -1e30f;
    #pragma unroll
    for (int q = 0; q < 24; q++) {
        float2 a = unpack2(acc2[32+q]);
        int j = 2*q;
        m = fmaxf(m, fmaxf(10.f * (a.x * sgd[j] + sbd[j]),
                           10.f * (a.y * sgd[j+1] + sbd[j+1])));
    }
    const float lstep = 0.08711371545f;  // ln(60)/47
    float sum = 0.f, dsum = 0.f;
    #pragma unroll
    for (int q = 0; q < 24; q++) {
        float2 a = unpack2(acc2[32+q]);
        int j = 2*q;
        float l0 = 10.f * (a.x * sgd[j]   + sbd[j]);
        float l1 = 10.f * (a.y * sgd[j+1] + sbd[j+1]);
        float e0 = __expf(l0 - m);
        float e1 = __expf(l1 - m);
        sum  += e0 + e1;
        dsum += e0 * __expf((float)j * lstep) + e1 * __expf((float)(j+1) * lstep);
    }
    float depth = dsum / sum;
    depth = fminf(fmaxf(depth, 1.0f), 65.0f);

    const float* K = intr + b * 9;
    float a00=K[0],a01=K[1],a02=K[2],a10=K[3],a11=K[4],a12=K[5],a20=K[6],a21=K[7],a22=K[8];
    float det = a00*(a11*a22 - a12*a21) - a01*(a10*a22 - a12*a20) + a02*(a10*a21 - a11*a20);
    float id = 1.0f / det;
    float i00 = (a11*a22 - a12*a21) * id;
    float i01 = (a02*a21 - a01*a22) * id;
    float i02 = (a01*a12 - a02*a11) * id;
    float i10 = (a12*a20 - a10*a22) * id;
    float i11 = (a00*a22 - a02*a20) * id;
    float i12 = (a02*a10 - a00*a12) * id;
    float i20 = (a10*a21 - a11*a20) * id;
    float i21 = (a01*a20 - a00*a21) * id;
    float i22 = (a00*a11 - a01*a10) * id;

    float py = (float)(p / W5i);
    float px = (float)(p - (p / W5i) * W5i);
    float cx = depth * (i00*px + i01*py + i02);
    float cy = depth * (i10*px + i11*py + i12);
    float cz = depth * (i20*px + i21*py + i22);

    const float* T = extr + b * 16;
    float ex = T[0]*cx + T[1]*cy + T[2]*cz  + T[3];
    float ey = T[4]*cx + T[5]*cy + T[6]*cz  + T[7];
    float ez = T[8]*cx + T[9]*cy + T[10]*cz + T[11];

    bool ev = (ex >= -51.2f) & (ex < 51.2f) & (ey >= -51.2f) & (ey < 51.2f)
            & (ez >= -5.0f)  & (ez < 3.0f);
    int bx = (int)floorf(ex / 0.4f + 64.0f);
    int by = (int)floorf(ey / 0.4f + 64.0f);
    bool gv = (bx >= 0) & (bx < 128) & (by >= 0) & (by < 128);

    if (ev & gv) {
        float wf = __expf(-0.05f * fabsf(ez));
        float* cell = g_bev + ((size_t)((b * 128 + by) * 128 + bx)) * BEVC;
        #pragma unroll
        for (int q = 0; q < 32; q++) {
            float2 a = unpack2(acc2[q]);
            float r0 = fmaxf(a.x * sg5[2*q+0] + sb5[2*q+0], 0.f) * wf;
            float r1 = fmaxf(a.y * sg5[2*q+1] + sb5[2*q+1], 0.f) * wf;
            atomicAdd(cell + 2*q+0, r0);
            atomicAdd(cell + 2*q+1, r1);
        }
    }
}

// ---------------------------------------------------------------------------
// Kernel C v4: 3x3 conv (64->128) + BN + ReLU.  (unchanged)
// ---------------------------------------------------------------------------
__global__ __launch_bounds__(256, 2)
void kC(const float* __restrict__ g, const float* __restrict__ bb,
        float* __restrict__ out)
{
    extern __shared__ __align__(16) float sm[];
    float* sin_ = sm;               // [ic 32][cell 612]  (18 x 34 tile)
    float* wbuf = sm + 32*612;      // [2][32ic * 32oc]
    int tid = threadIdx.x;
    int tx = tid & 31, ty = tid >> 5;        // ty 0..7
    int x0 = blockIdx.x * 32, y0 = blockIdx.y * 16;
    int bz = blockIdx.z;                     // 0..47
    int b = bz >> 2;
    int oc0 = (bz & 3) * 32;

    const float4* bev4 = (const float4*)g_bev;

    for (int i = tid; i < 612*8; i += 256) {
        int icg = i & 7;
        int cell = i >> 3;
        int iy = cell / 34, ix = cell - iy * 34;
        int gy = y0 + iy - 1, gx = x0 + ix - 1;
        float4 v = make_float4(0.f, 0.f, 0.f, 0.f);
        if (gy >= 0 && gy < 128 && gx >= 0 && gx < 128)
            v = bev4[((((size_t)b * 128 + gy) * 128 + gx) << 4) + icg];
        sin_[(icg*4+0)*612 + cell] = v.x;
        sin_[(icg*4+1)*612 + cell] = v.y;
        sin_[(icg*4+2)*612 + cell] = v.z;
        sin_[(icg*4+3)*612 + cell] = v.w;
    }
    for (int i = tid; i < 1024; i += 256) {
        int icl = i >> 5, oc = i & 31;
        wbuf[i] = g_wt[(0*64 + 0*32 + icl)*128 + oc0 + oc];
    }
    __syncthreads();

    u64 acc[2][16];
    #pragma unroll
    for (int q = 0; q < 16; q++) { acc[0][q] = 0ull; acc[1][q] = 0ull; }

    for (int s = 0; s < 18; s++) {
        int buf = s & 1;
        if (s < 17) {
            int sn = s + 1;
            int kkn = (sn >= 9) ? sn - 9 : sn;
            int chn = (sn >= 9) ? 1 : 0;
            float* wdst = wbuf + (buf ^ 1) * 1024;
            for (int i = tid; i < 1024; i += 256) {
                int icl = i >> 5, oc = i & 31;
                wdst[i] = g_wt[(kkn*64 + chn*32 + icl)*128 + oc0 + oc];
            }
        }
        int kk = (s >= 9) ? s - 9 : s;
        int ky = kk / 3, kx = kk - ky*3;
        int base0 = (ty + ky) * 34 + tx + kx;
        int base1 = base0 + 8 * 34;
        const ulonglong2* wb = (const ulonglong2*)(wbuf + buf * 1024);
        #pragma unroll 4
        for (int ic = 0; ic < 32; ic++) {
            float xv0 = sin_[ic * 612 + base0];
            float xv1 = sin_[ic * 612 + base1];
            u64 x0p = pack2(xv0, xv0);
            u64 x1p = pack2(xv1, xv1);
            const ulonglong2* wrow = wb + ic*8;
            #pragma unroll
            for (int q = 0; q < 8; q++) {
                ulonglong2 wv = wrow[q];
                fma2(acc[0][2*q+0], x0p, wv.x);
                fma2(acc[0][2*q+1], x0p, wv.y);
                fma2(acc[1][2*q+0], x1p, wv.x);
                fma2(acc[1][2*q+1], x1p, wv.y);
            }
        }
        __syncthreads();
        if (s == 8) {
            for (int i = tid; i < 612*8; i += 256) {
                int icg = (i & 7) + 8;
                int cell = i >> 3;
                int iy = cell / 34, ix = cell - iy * 34;
                int gy = y0 + iy - 1, gx = x0 + ix - 1;
                float4 v = make_float4(0.f, 0.f, 0.f, 0.f);
                if (gy >= 0 && gy < 128 && gx >= 0 && gx < 128)
                    v = bev4[((((size_t)b * 128 + gy) * 128 + gx) << 4) + icg];
                int icl = i & 7;
                sin_[(icl*4+0)*612 + cell] = v.x;
                sin_[(icl*4+1)*612 + cell] = v.y;
                sin_[(icl*4+2)*612 + cell] = v.z;
                sin_[(icl*4+3)*612 + cell] = v.w;
            }
            __syncthreads();
        }
    }

    #pragma unroll
    for (int px = 0; px < 2; px++) {
        float* op = out + (((size_t)b * 128 + oc0) * 128 + (y0 + ty + px*8)) * 128 + (x0 + tx);
        #pragma unroll
        for (int q = 0; q < 16; q++) {
            float2 a = unpack2(acc[px][q]);
            int o = 2*q;
            op[(size_t)(o+0) * 16384] = fmaxf(a.x * g[oc0 + o]     + bb[oc0 + o],     0.f);
            op[(size_t)(o+1) * 16384] = fmaxf(a.y * g[oc0 + o + 1] + bb[oc0 + o + 1], 0.f);
        }
    }
}

// ---------------------------------------------------------------------------
extern "C" void kernel_launch(void* const* d_in, const int* in_sizes, int n_in,
                              void* d_out, int out_size)
{
    const float* stage1 = (const float*)d_in[0];
    const float* stage5 = (const float*)d_in[1];
    const float* intr   = (const float*)d_in[2];
    const float* extr   = (const float*)d_in[3];
    const float* red1_w = (const float*)d_in[4];
    const float* red1_g = (const float*)d_in[5];
    const float* red1_b = (const float*)d_in[6];
    const float* skip_w = (const float*)d_in[7];
    const float* skip_g = (const float*)d_in[8];
    const float* skip_b = (const float*)d_in[9];
    const float* red5_w = (const float*)d_in[10];
    const float* red5_g = (const float*)d_in[11];
    const float* red5_b = (const float*)d_in[12];
    const float* dep5_w = (const float*)d_in[13];
    const float* dep5_g = (const float*)d_in[14];
    const float* dep5_b = (const float*)d_in[15];
    const float* main_w = (const float*)d_in[16];
    const float* main_g = (const float*)d_in[17];
    const float* main_b = (const float*)d_in[18];

    float* out_main = (float*)d_out;
    float* out_skip = (float*)d_out + OUT_MAIN;

    // side stream + events (created once; creation is not a captured op)
    static cudaStream_t s1 = nullptr;
    static cudaEvent_t eFork = nullptr, eJoin = nullptr;
    if (!s1) {
        cudaStreamCreateWithFlags(&s1, cudaStreamNonBlocking);
        cudaEventCreateWithFlags(&eFork, cudaEventDisableTiming);
        cudaEventCreateWithFlags(&eJoin, cudaEventDisableTiming);
    }

    // zero BEV scratch (critical path start)
    void* bevPtr = nullptr;
    cudaGetSymbolAddress(&bevPtr, g_bev);
    cudaMemsetAsync(bevPtr, 0, sizeof(float) * (size_t)Bn * 128 * 128 * BEVC);

    // fork: skip path runs concurrently on s1
    cudaEventRecord(eFork, 0);
    cudaStreamWaitEvent(s1, eFork, 0);
    kA<<<(Bn * HW1) / 256, 128, 0, s1>>>(stage1, red1_w, red1_g, red1_b,
                                         skip_w, skip_g, skip_b, out_skip);
    cudaEventRecord(eJoin, s1);

    // critical path: weight prep + fused lift (single stage5 pass)
    kWt<<<512, 256>>>(main_w, red5_w, dep5_w);
    kB<<<Bn * 88, 128>>>(stage5, red5_g, red5_b, dep5_g, dep5_b, intr, extr);

    // join before kC
    cudaStreamWaitEvent(0, eJoin, 0);

    // BEV conv v4: 2 blocks/SM
    int smem = (32*612 + 2*1024) * sizeof(float);   // 86528
    cudaFuncSetAttribute(kC, cudaFuncAttributeMaxDynamicSharedMemorySize, smem);
    dim3 gridC(4, 8, Bn * 4);
    kC<<<gridC, 256, smem>>>(main_g, main_b, out_main);
}